// round 8
// baseline (speedup 1.0000x reference)
#include <cuda_runtime.h>
#include <math.h>

#define NMAX  8192
#define TILE  1024
#define NTMAX 8
#define NBKT  2048
#define TPB   448      // 16 j-lanes x 28 row-pair slots
#define SLOTS 28
#define GMAX  160

__device__ float st_yt[NMAX];     // sorted-ish ascending by yt
__device__ float st_u [NMAX];     // u = yp * 20*log2e
__device__ float st_z [NMAX];     // z = -u*yt
__device__ float st_p [NMAX];     // yp = pred*20
__device__ float g_tmin[NTMAX], g_tmax[NTMAX];
__device__ float g_ymin;
__device__ float2 g_part[GMAX];
__device__ int   g_done;          // zero-init; reset by last block each run

__device__ __forceinline__ float ex2a(float x) {
    float r; asm("ex2.approx.f32 %0, %1;" : "=f"(r) : "f"(x)); return r;
}

// ---------------- Kernel 1: bucket sort + tile min/max -----------------------
__global__ void __launch_bounds__(1024) pro_sort(const float* __restrict__ pred,
                                                 const float* __restrict__ ytg,
                                                 int n, int padn, int nt)
{
    __shared__ int sa[NBKT], sb[NBKT];
    const float K1 = 28.853900817779268f;   // 20 * log2(e)
    int t = threadIdx.x;

    sa[t] = 0; sa[t + 1024] = 0;
    __syncthreads();

    for (int i = t; i < n; i += 1024) {
        float y = ytg[i];
        int b = (int)floorf(y * (float)NBKT);
        b = max(0, min(NBKT - 1, b));
        atomicAdd(&sa[b], 1);
    }
    __syncthreads();

    // inclusive Hillis-Steele scan over NBKT counts (double buffered)
    int* A = sa; int* B = sb;
    for (int off = 1; off < NBKT; off <<= 1) {
        for (int idx = t; idx < NBKT; idx += 1024)
            B[idx] = A[idx] + ((idx >= off) ? A[idx - off] : 0);
        __syncthreads();
        int* tmp = A; A = B; B = tmp;
    }
    // A = inclusive scan; reuse B as per-bucket running offsets
    B[t] = 0; B[t + 1024] = 0;
    __syncthreads();

    for (int i = t; i < n; i += 1024) {
        float y  = ytg[i];
        float yp = pred[i] * 20.0f;
        float u  = pred[i] * K1;
        int b = (int)floorf(y * (float)NBKT);
        b = max(0, min(NBKT - 1, b));
        int pos = ((b > 0) ? A[b - 1] : 0) + atomicAdd(&B[b], 1);
        st_yt[pos] = y; st_u[pos] = u; st_z[pos] = -u * y; st_p[pos] = yp;
    }
    for (int i = n + t; i < padn; i += 1024) {
        st_yt[i] = 1e30f; st_u[i] = 0.0f; st_z[i] = 0.0f; st_p[i] = 0.0f;
    }
    __syncthreads();

    // exact per-tile min/max (one warp per tile)
    int w = t >> 5, l = t & 31;
    if (w < nt) {
        float mn = 1e30f, mx = -1e30f;
        for (int i = l; i < TILE; i += 32) {
            float y = st_yt[w * TILE + i];
            mn = fminf(mn, y); mx = fmaxf(mx, y);
        }
        #pragma unroll
        for (int o = 16; o; o >>= 1) {
            mn = fminf(mn, __shfl_xor_sync(0xffffffffu, mn, o));
            mx = fmaxf(mx, __shfl_xor_sync(0xffffffffu, mx, o));
        }
        if (l == 0) { g_tmin[w] = mn; g_tmax[w] = mx; }
    }
    __syncthreads();
    if (t == 0) {
        float m = 1e30f;
        for (int i = 0; i < nt; i++) m = fminf(m, g_tmin[i]);
        g_ymin = m;
    }
}

// ---------------- Kernel 2: classified O(N^2) pass + fused finish ------------
__global__ void __launch_bounds__(TPB) pro_main(float* __restrict__ out,
                                                int n, int nt, int grid)
{
    __shared__ __align__(16) float su[TILE], sz[TILE], sy[TILE];
    __shared__ float tmn[NTMAX], tmx[NTMAX];
    __shared__ float rlp[SLOTS], rct[SLOTS];
    __shared__ int   s_last;
    __shared__ float ft[16], fc[16];

    const float EPS = 1e-8f;
    int t  = threadIdx.x;
    int tx = t & 15;
    int ty = t >> 4;
    int q  = blockIdx.x * SLOTS + ty;
    int rA = q, rB = n - 1 - q;
    bool hasA = (2 * q <= n - 1);
    bool hasB = (2 * q <  n - 1);

    if (t < nt) { tmn[t] = g_tmin[t]; tmx[t] = g_tmax[t]; }

    float ytA = 0.0f, ypA = 0.0f, eA = -1e30f;
    float ytB = 0.0f, ypB = 0.0f, eB = -1e30f;
    if (hasA) { ytA = st_yt[rA]; ypA = st_p[rA]; eA = ytA - EPS; }
    if (hasB) { ytB = st_yt[rB]; ypB = st_p[rB]; eB = ytB - EPS; }

    float a0 = 0.0f, a1 = 0.0f;   // row A accumulators
    float b0 = 0.0f, b1 = 0.0f;   // row B accumulators

    for (int tt = 0; tt < nt; tt++) {
        __syncthreads();
        for (int i = t; i < TILE; i += TPB) {
            int gi = tt * TILE + i;
            su[i] = st_u[gi]; sz[i] = st_z[gi]; sy[i] = st_yt[gi];
        }
        __syncthreads();

        const float4* su4 = (const float4*)su;
        const float4* sz4 = (const float4*)sz;
        const float4* sy4 = (const float4*)sy;
        float mnt = tmn[tt], mxt = tmx[tt];

        // ---- row A ----
        if (hasA && mnt < eA) {
            if (mxt < eA) {            // all valid: no mask instructions
                #pragma unroll 4
                for (int i = tx; i < TILE / 4; i += 16) {
                    float4 u4 = su4[i], z4 = sz4[i];
                    a0 += ex2a(fmaf(ytA, u4.x, z4.x));
                    a1 += ex2a(fmaf(ytA, u4.y, z4.y));
                    a0 += ex2a(fmaf(ytA, u4.z, z4.z));
                    a1 += ex2a(fmaf(ytA, u4.w, z4.w));
                }
            } else {                   // boundary: masked
                #pragma unroll 4
                for (int i = tx; i < TILE / 4; i += 16) {
                    float4 u4 = su4[i], z4 = sz4[i], y4 = sy4[i];
                    float v0 = ex2a(fmaf(ytA, u4.x, z4.x));
                    float v1 = ex2a(fmaf(ytA, u4.y, z4.y));
                    float v2 = ex2a(fmaf(ytA, u4.z, z4.z));
                    float v3 = ex2a(fmaf(ytA, u4.w, z4.w));
                    if (y4.x < eA) a0 += v0;
                    if (y4.y < eA) a1 += v1;
                    if (y4.z < eA) a0 += v2;
                    if (y4.w < eA) a1 += v3;
                }
            }
        }
        // ---- row B ----
        if (hasB && mnt < eB) {
            if (mxt < eB) {
                #pragma unroll 4
                for (int i = tx; i < TILE / 4; i += 16) {
                    float4 u4 = su4[i], z4 = sz4[i];
                    b0 += ex2a(fmaf(ytB, u4.x, z4.x));
                    b1 += ex2a(fmaf(ytB, u4.y, z4.y));
                    b0 += ex2a(fmaf(ytB, u4.z, z4.z));
                    b1 += ex2a(fmaf(ytB, u4.w, z4.w));
                }
            } else {
                #pragma unroll 4
                for (int i = tx; i < TILE / 4; i += 16) {
                    float4 u4 = su4[i], z4 = sz4[i], y4 = sy4[i];
                    float v0 = ex2a(fmaf(ytB, u4.x, z4.x));
                    float v1 = ex2a(fmaf(ytB, u4.y, z4.y));
                    float v2 = ex2a(fmaf(ytB, u4.z, z4.z));
                    float v3 = ex2a(fmaf(ytB, u4.w, z4.w));
                    if (y4.x < eB) b0 += v0;
                    if (y4.y < eB) b1 += v1;
                    if (y4.z < eB) b0 += v2;
                    if (y4.w < eB) b1 += v3;
                }
            }
        }
    }

    // ---- reduce the 16 j-lanes per slot (all threads participate) ----
    float sA = a0 + a1;
    float sB = b0 + b1;
    #pragma unroll
    for (int o = 1; o < 16; o <<= 1) {
        sA += __shfl_xor_sync(0xffffffffu, sA, o);
        sB += __shfl_xor_sync(0xffffffffu, sB, o);
    }

    if (tx == 0) {
        float lp = 0.0f, c = 0.0f;
        float ymin = g_ymin;
        if (hasA) {
            float d = ytA - ymin;
            if (d > EPS) { float l0 = ypA * d; lp += l0 - logf(expf(l0) + sA); c += 1.0f; }
        }
        if (hasB) {
            float d = ytB - ymin;
            if (d > EPS) { float l1 = ypB * d; lp += l1 - logf(expf(l1) + sB); c += 1.0f; }
        }
        rlp[ty] = lp; rct[ty] = c;
    }
    __syncthreads();

    // ---- publish per-CTA partial, elect last block ----
    if (t == 0) {
        float tot = 0.0f, c = 0.0f;
        #pragma unroll
        for (int i = 0; i < SLOTS; i++) { tot += rlp[i]; c += rct[i]; }
        g_part[blockIdx.x] = make_float2(tot, c);
        __threadfence();
        int done = atomicAdd(&g_done, 1);
        s_last = (done == grid - 1) ? 1 : 0;
    }
    __syncthreads();

    // ---- last block: deterministic final reduce ----
    if (s_last) {
        __threadfence();
        float tot = 0.0f, cnt = 0.0f;
        if (t < grid) { float2 p = g_part[t]; tot = p.x; cnt = p.y; }
        #pragma unroll
        for (int o = 16; o; o >>= 1) {        // all threads, full warps
            tot += __shfl_xor_sync(0xffffffffu, tot, o);
            cnt += __shfl_xor_sync(0xffffffffu, cnt, o);
        }
        if ((t & 31) == 0) { ft[t >> 5] = tot; fc[t >> 5] = cnt; }
        __syncthreads();
        if (t == 0) {
            float a = 0.0f, b = 0.0f;
            #pragma unroll
            for (int i = 0; i < TPB / 32; i++) { a += ft[i]; b += fc[i]; }
            out[0] = (b > 0.0f) ? (-a / b) : 0.0f;
            g_done = 0;   // restore for next graph replay
        }
    }
}

// ---------------- Launch ------------------------------------------------------
extern "C" void kernel_launch(void* const* d_in, const int* in_sizes, int n_in,
                              void* d_out, int out_size)
{
    const float* pred = (const float*)d_in[0];   // predict_similarity
    const float* yt   = (const float*)d_in[1];   // true_similarity
    int n = in_sizes[0];
    if (n > NMAX) n = NMAX;
    int nt   = (n + TILE - 1) / TILE;            // 8 for n=8192
    int padn = nt * TILE;
    int nh   = (n + 1) / 2;
    int grid = (nh + SLOTS - 1) / SLOTS;         // 147 for n=8192
    if (grid > GMAX) grid = GMAX;

    pro_sort<<<1, 1024>>>(pred, yt, n, padn, nt);
    pro_main<<<grid, TPB>>>((float*)d_out, n, nt, grid);
}

// round 9
// speedup vs baseline: 1.2106x; 1.2106x over previous
#include <cuda_runtime.h>
#include <math.h>

#define NMAX  8192
#define NBKT  2048
#define TPB   448     // 14 warps; 1 warp = 1 row-pair slot
#define SLOTS 14
#define GMAX  512

__device__ float2 st_uz[NMAX];        // sorted-by-yt: (u = yp*20*log2e, z = -u*yt)
__device__ float  st_yt[NMAX];        // sorted yt
__device__ float  st_p [NMAX];        // sorted yp = pred*20
__device__ int    g_boff[NBKT + 1];   // bucket rank offsets (exclusive scan)
__device__ float  g_ymin;
__device__ float2 g_part[GMAX];
__device__ int    g_done;             // zero-init; reset by last block each run

__device__ __forceinline__ float ex2a(float x) {
    float r; asm("ex2.approx.f32 %0, %1;" : "=f"(r) : "f"(x)); return r;
}

// ------------- Prep: 2048-bucket counting scatter + offsets + global min ----
__global__ void __launch_bounds__(1024) pro_prep(const float* __restrict__ pred,
                                                 const float* __restrict__ ytg,
                                                 int n, int padn)
{
    __shared__ int HA[NBKT], HB[NBKT];
    __shared__ float smn[32];
    const float K1 = 28.853900817779268f;   // 20 * log2(e)
    int t = threadIdx.x;

    HA[t] = 0; HA[t + 1024] = 0;
    __syncthreads();

    float mn = 1e30f;
    for (int i = t; i < n; i += 1024) {
        float y = ytg[i];
        mn = fminf(mn, y);
        int b = min(NBKT - 1, max(0, (int)floorf(y * (float)NBKT)));
        atomicAdd(&HA[b], 1);
    }
    __syncthreads();

    // inclusive Hillis-Steele scan (double buffered, no in-pass hazards)
    int* pa = HA; int* pb = HB;
    for (int off = 1; off < NBKT; off <<= 1) {
        for (int i = t; i < NBKT; i += 1024)
            pb[i] = pa[i] + ((i >= off) ? pa[i - off] : 0);
        __syncthreads();
        int* tmp = pa; pa = pb; pb = tmp;
    }
    if (t == 0) g_boff[0] = 0;
    for (int i = t; i < NBKT; i += 1024) g_boff[i + 1] = pa[i];
    for (int i = t; i < NBKT; i += 1024) pb[i] = (i > 0) ? pa[i - 1] : 0;  // running offsets
    __syncthreads();

    for (int i = t; i < n; i += 1024) {
        float y = ytg[i], pr = pred[i];
        int b = min(NBKT - 1, max(0, (int)floorf(y * (float)NBKT)));
        int pos = atomicAdd(&pb[b], 1);
        float u = pr * K1;
        st_uz[pos] = make_float2(u, -u * y);
        st_yt[pos] = y;
        st_p [pos] = pr * 20.0f;
    }
    for (int i = n + t; i < padn; i += 1024) {
        st_uz[i] = make_float2(0.0f, 0.0f);
        st_yt[i] = 1e30f;
    }

    // block min -> g_ymin
    #pragma unroll
    for (int o = 16; o; o >>= 1) mn = fminf(mn, __shfl_xor_sync(0xffffffffu, mn, o));
    if ((t & 31) == 0) smn[t >> 5] = mn;
    __syncthreads();
    if (t < 32) {   // full warp, full mask
        float v = smn[t];
        #pragma unroll
        for (int o = 16; o; o >>= 1) v = fminf(v, __shfl_xor_sync(0xffffffffu, v, o));
        if (t == 0) g_ymin = v;
    }
}

// ------------- Main: prefix fast loops + tiny masked bucket + fused finish --
__global__ void __launch_bounds__(TPB) pro_main(float* __restrict__ out,
                                                int n, int grid)
{
    __shared__ float rlp[SLOTS], rct[SLOTS];
    __shared__ int   s_last;
    __shared__ float ft[SLOTS], fc[SLOTS];

    const float EPS = 1e-8f;
    int t = threadIdx.x, w = t >> 5, l = t & 31;
    int q = blockIdx.x * SLOTS + w;

    bool hasA = (2 * q <= n - 1);
    bool hasB = (2 * q <  n - 1);
    int rA = q, rB = n - 1 - q;

    float ytA = 0.f, ypA = 0.f, eA = 0.f; int cLoA = 0, cHiA = 0;
    float ytB = 0.f, ypB = 0.f, eB = 0.f; int cLoB = 0, cHiB = 0;
    if (hasA) {
        ytA = st_yt[rA]; ypA = st_p[rA]; eA = ytA - EPS;
        int b = min(NBKT - 1, max(0, (int)floorf(eA * (float)NBKT)));
        cLoA = g_boff[b]; cHiA = g_boff[b + 1];
    }
    if (hasB) {
        ytB = st_yt[rB]; ypB = st_p[rB]; eB = ytB - EPS;
        int b = min(NBKT - 1, max(0, (int)floorf(eB * (float)NBKT)));
        cLoB = g_boff[b]; cHiB = g_boff[b + 1];
    } else { ytB = ytA; eB = eA; cLoB = cLoA; cHiB = cLoA; }  // duplicate A, discarded

    float aA = 0.f, aA2 = 0.f, aB = 0.f, aB2 = 0.f;
    const float4* uz4 = (const float4*)st_uz;
    const float4* yt4 = (const float4*)st_yt;

    // sorted order guarantees cLoA <= cLoB (ytA <= ytB)
    int G1  = cLoA >> 2;            // groups fully valid for BOTH rows
    int G2  = cLoB >> 2;            // groups fully valid for B
    int GHA = (cHiA + 3) >> 2;      // end of A's masked bucket region
    int GHB = (cHiB + 3) >> 2;

    if (hasA) {
        // shared fast: one load pair serves 8 exps, no masks
        #pragma unroll 2
        for (int g = l; g < G1; g += 32) {
            float4 p0 = uz4[2 * g], p1 = uz4[2 * g + 1];
            aA  += ex2a(fmaf(ytA, p0.x, p0.y));
            aA2 += ex2a(fmaf(ytA, p0.z, p0.w));
            aA  += ex2a(fmaf(ytA, p1.x, p1.y));
            aA2 += ex2a(fmaf(ytA, p1.z, p1.w));
            aB  += ex2a(fmaf(ytB, p0.x, p0.y));
            aB2 += ex2a(fmaf(ytB, p0.z, p0.w));
            aB  += ex2a(fmaf(ytB, p1.x, p1.y));
            aB2 += ex2a(fmaf(ytB, p1.z, p1.w));
        }
        // B-only fast
        #pragma unroll 2
        for (int g = G1 + l; g < G2; g += 32) {
            float4 p0 = uz4[2 * g], p1 = uz4[2 * g + 1];
            aB  += ex2a(fmaf(ytB, p0.x, p0.y));
            aB2 += ex2a(fmaf(ytB, p0.z, p0.w));
            aB  += ex2a(fmaf(ytB, p1.x, p1.y));
            aB2 += ex2a(fmaf(ytB, p1.z, p1.w));
        }
        // A masked (row A's own bucket: ~4 elements)
        for (int g = G1 + l; g < GHA; g += 32) {
            float4 p0 = uz4[2 * g], p1 = uz4[2 * g + 1];
            float4 y4 = yt4[g];
            float v0 = ex2a(fmaf(ytA, p0.x, p0.y));
            float v1 = ex2a(fmaf(ytA, p0.z, p0.w));
            float v2 = ex2a(fmaf(ytA, p1.x, p1.y));
            float v3 = ex2a(fmaf(ytA, p1.z, p1.w));
            if (y4.x < eA) aA  += v0;
            if (y4.y < eA) aA2 += v1;
            if (y4.z < eA) aA  += v2;
            if (y4.w < eA) aA2 += v3;
        }
        // B masked
        for (int g = G2 + l; g < GHB; g += 32) {
            float4 p0 = uz4[2 * g], p1 = uz4[2 * g + 1];
            float4 y4 = yt4[g];
            float v0 = ex2a(fmaf(ytB, p0.x, p0.y));
            float v1 = ex2a(fmaf(ytB, p0.z, p0.w));
            float v2 = ex2a(fmaf(ytB, p1.x, p1.y));
            float v3 = ex2a(fmaf(ytB, p1.z, p1.w));
            if (y4.x < eB) aB  += v0;
            if (y4.y < eB) aB2 += v1;
            if (y4.z < eB) aB  += v2;
            if (y4.w < eB) aB2 += v3;
        }
    }

    // warp reduce (full warp, full mask)
    float sA = aA + aA2;
    float sB = aB + aB2;
    #pragma unroll
    for (int o = 16; o; o >>= 1) {
        sA += __shfl_xor_sync(0xffffffffu, sA, o);
        sB += __shfl_xor_sync(0xffffffffu, sB, o);
    }

    if (l == 0) {
        float lp = 0.f, c = 0.f;
        float ymin = g_ymin;
        if (hasA) {
            float d = ytA - ymin;
            if (d > EPS) { float l0 = ypA * d; lp += l0 - logf(expf(l0) + sA); c += 1.f; }
        }
        if (hasB) {
            float d = ytB - ymin;
            if (d > EPS) { float l1 = ypB * d; lp += l1 - logf(expf(l1) + sB); c += 1.f; }
        }
        rlp[w] = lp; rct[w] = c;
    }
    __syncthreads();

    // publish per-CTA partial, elect last block
    if (t == 0) {
        float tot = 0.f, c = 0.f;
        #pragma unroll
        for (int i = 0; i < SLOTS; i++) { tot += rlp[i]; c += rct[i]; }
        g_part[blockIdx.x] = make_float2(tot, c);
        __threadfence();
        int done = atomicAdd(&g_done, 1);
        s_last = (done == grid - 1) ? 1 : 0;
    }
    __syncthreads();

    // last block: deterministic final reduce
    if (s_last) {
        __threadfence();
        float tot = 0.f, cnt = 0.f;
        for (int i = t; i < grid; i += TPB) {
            float2 p = g_part[i]; tot += p.x; cnt += p.y;
        }
        #pragma unroll
        for (int o = 16; o; o >>= 1) {            // all threads, full warps
            tot += __shfl_xor_sync(0xffffffffu, tot, o);
            cnt += __shfl_xor_sync(0xffffffffu, cnt, o);
        }
        if ((t & 31) == 0) { ft[t >> 5] = tot; fc[t >> 5] = cnt; }
        __syncthreads();
        if (t == 0) {
            float a = 0.f, b = 0.f;
            #pragma unroll
            for (int i = 0; i < SLOTS; i++) { a += ft[i]; b += fc[i]; }
            out[0] = (b > 0.f) ? (-a / b) : 0.0f;
            g_done = 0;   // restore for next graph replay
        }
    }
}

// ------------- Launch ---------------------------------------------------------
extern "C" void kernel_launch(void* const* d_in, const int* in_sizes, int n_in,
                              void* d_out, int out_size)
{
    const float* pred = (const float*)d_in[0];   // predict_similarity
    const float* yt   = (const float*)d_in[1];   // true_similarity
    int n = in_sizes[0];
    if (n > NMAX) n = NMAX;
    int padn = (n + 3) & ~3;                     // group-aligned padding
    if (padn > NMAX) padn = NMAX;

    int nslots = (n + 1) / 2;                    // 4096 for n=8192
    int grid = (nslots + SLOTS - 1) / SLOTS;     // 293
    if (grid > GMAX) grid = GMAX;

    pro_prep<<<1, 1024>>>(pred, yt, n, padn);
    pro_main<<<grid, TPB>>>((float*)d_out, n, grid);
}

// round 10
// speedup vs baseline: 1.5141x; 1.2507x over previous
#include <cuda_runtime.h>
#include <math.h>

#define NMAX  8192
#define NBKT  1024
#define TPB   448     // 14 warps; 1 warp = 1 row-pair slot
#define SLOTS 14
#define GMAX  512

__device__ float st_u [NMAX];         // sorted-by-yt: u = yp*20*log2e
__device__ float st_z [NMAX];         // z = -u*yt
__device__ float st_yt[NMAX];         // sorted yt
__device__ int   g_boff[NBKT + 1];    // bucket rank offsets
__device__ float g_ymin;
__device__ float2 g_part[GMAX];
__device__ int   g_done;              // zero-init; reset by last block each run

__device__ __forceinline__ float ex2a(float x) {
    float r; asm("ex2.approx.f32 %0, %1;" : "=f"(r) : "f"(x)); return r;
}

// ------------- Prep: counting sort staged through smem ----------------------
__global__ void __launch_bounds__(1024) pro_prep(const float* __restrict__ pred,
                                                 const float* __restrict__ ytg,
                                                 int n, int padn)
{
    __shared__ int   HA[NBKT], HB[NBKT];   // 8 KB
    __shared__ float SG[NMAX];             // 32 KB stage
    __shared__ float smn[32];
    const float K1 = 28.853900817779268f;  // 20 * log2(e)
    int t = threadIdx.x;

    HA[t] = 0;
    __syncthreads();

    float ry[8], rp[8];
    int   rb[8], rpos[8];
    float mn = 1e30f;

    #pragma unroll
    for (int e = 0; e < 8; e++) {
        int i = t + e * 1024;
        if (i < n) {
            float y = ytg[i], p = pred[i];
            ry[e] = y; rp[e] = p;
            int b = min(NBKT - 1, max(0, (int)floorf(y * (float)NBKT)));
            rb[e] = b;
            atomicAdd(&HA[b], 1);
            mn = fminf(mn, y);
        } else { ry[e] = 0.f; rp[e] = 0.f; rb[e] = -1; }
    }
    __syncthreads();

    // inclusive scan over 1024 buckets (1 elem/thread, double buffered, 10 iters)
    int* pa = HA; int* pb = HB;
    #pragma unroll
    for (int off = 1; off < NBKT; off <<= 1) {
        pb[t] = pa[t] + ((t >= off) ? pa[t - off] : 0);
        __syncthreads();
        int* tmp = pa; pa = pb; pb = tmp;
    }
    if (t == 0) g_boff[0] = 0;
    g_boff[t + 1] = pa[t];
    pb[t] = (t > 0) ? pa[t - 1] : 0;       // per-bucket running cursors
    __syncthreads();

    #pragma unroll
    for (int e = 0; e < 8; e++)
        if (rb[e] >= 0) rpos[e] = atomicAdd(&pb[rb[e]], 1);
    __syncthreads();

    // pass 1: u
    #pragma unroll
    for (int e = 0; e < 8; e++) if (rb[e] >= 0) SG[rpos[e]] = rp[e] * K1;
    __syncthreads();
    #pragma unroll
    for (int e = 0; e < 8; e++) { int i = t + e * 1024; if (i < n) st_u[i] = SG[i]; }
    __syncthreads();
    // pass 2: z = -u*yt
    #pragma unroll
    for (int e = 0; e < 8; e++) if (rb[e] >= 0) SG[rpos[e]] = -(rp[e] * K1) * ry[e];
    __syncthreads();
    #pragma unroll
    for (int e = 0; e < 8; e++) { int i = t + e * 1024; if (i < n) st_z[i] = SG[i]; }
    __syncthreads();
    // pass 3: yt
    #pragma unroll
    for (int e = 0; e < 8; e++) if (rb[e] >= 0) SG[rpos[e]] = ry[e];
    __syncthreads();
    #pragma unroll
    for (int e = 0; e < 8; e++) { int i = t + e * 1024; if (i < n) st_yt[i] = SG[i]; }
    // padding
    for (int i = n + t; i < padn; i += 1024) { st_u[i] = 0.f; st_z[i] = 0.f; st_yt[i] = 1e30f; }

    // global min
    #pragma unroll
    for (int o = 16; o; o >>= 1) mn = fminf(mn, __shfl_xor_sync(0xffffffffu, mn, o));
    if ((t & 31) == 0) smn[t >> 5] = mn;
    __syncthreads();
    if (t < 32) {
        float v = smn[t];
        #pragma unroll
        for (int o = 16; o; o >>= 1) v = fminf(v, __shfl_xor_sync(0xffffffffu, v, o));
        if (t == 0) g_ymin = v;
    }
}

// ------------- Main: pipelined fast loops + tiny masked bucket --------------
__global__ void __launch_bounds__(TPB) pro_main(float* __restrict__ out,
                                                int n, int grid)
{
    __shared__ float rlp[SLOTS], rct[SLOTS];
    __shared__ int   s_last;
    __shared__ float ft[SLOTS], fc[SLOTS];

    const float EPS = 1e-8f;
    int t = threadIdx.x, w = t >> 5, l = t & 31;
    int q = blockIdx.x * SLOTS + w;

    bool hasA = (2 * q <= n - 1);
    bool hasB = (2 * q <  n - 1);
    int rA = q, rB = n - 1 - q;

    float ytA = 0.f, uA = 0.f, eA = 0.f; int cLoA = 0, cHiA = 0;
    float ytB = 0.f, uB = 0.f, eB = 0.f; int cLoB = 0, cHiB = 0;
    if (hasA) {
        ytA = st_yt[rA]; uA = st_u[rA]; eA = ytA - EPS;
        int b = min(NBKT - 1, max(0, (int)floorf(eA * (float)NBKT)));
        cLoA = g_boff[b]; cHiA = g_boff[b + 1];
    }
    if (hasB) {
        ytB = st_yt[rB]; uB = st_u[rB]; eB = ytB - EPS;
        int b = min(NBKT - 1, max(0, (int)floorf(eB * (float)NBKT)));
        cLoB = g_boff[b]; cHiB = g_boff[b + 1];
    } else { ytB = ytA; eB = eA; cLoB = cLoA; cHiB = cLoA; }

    float aA = 0.f, aA2 = 0.f, aB = 0.f, aB2 = 0.f;
    const float4* su4 = (const float4*)st_u;
    const float4* sz4 = (const float4*)st_z;
    const float4* sy4 = (const float4*)st_yt;

    int G1  = cLoA >> 2;            // groups fully valid for BOTH rows
    int G2  = cLoB >> 2;            // groups fully valid for B
    int GHA = (cHiA + 3) >> 2;
    int GHB = (cHiB + 3) >> 2;

    if (hasA) {
        // ---- shared fast loop (both rows), software pipelined ----
        int g = l;
        if (g < G1) {
            float4 u0 = su4[g], z0 = sz4[g];
            while (true) {
                int  gn   = g + 32;
                bool more = gn < G1;
                int  gc   = more ? gn : g;
                float4 un = su4[gc], zn = sz4[gc];   // prefetch next
                aA  += ex2a(fmaf(ytA, u0.x, z0.x));
                aA2 += ex2a(fmaf(ytA, u0.y, z0.y));
                aA  += ex2a(fmaf(ytA, u0.z, z0.z));
                aA2 += ex2a(fmaf(ytA, u0.w, z0.w));
                aB  += ex2a(fmaf(ytB, u0.x, z0.x));
                aB2 += ex2a(fmaf(ytB, u0.y, z0.y));
                aB  += ex2a(fmaf(ytB, u0.z, z0.z));
                aB2 += ex2a(fmaf(ytB, u0.w, z0.w));
                if (!more) break;
                u0 = un; z0 = zn; g = gn;
            }
        }
        // ---- B-only fast loop, software pipelined ----
        g = G1 + l;
        if (g < G2) {
            float4 u0 = su4[g], z0 = sz4[g];
            while (true) {
                int  gn   = g + 32;
                bool more = gn < G2;
                int  gc   = more ? gn : g;
                float4 un = su4[gc], zn = sz4[gc];
                aB  += ex2a(fmaf(ytB, u0.x, z0.x));
                aB2 += ex2a(fmaf(ytB, u0.y, z0.y));
                aB  += ex2a(fmaf(ytB, u0.z, z0.z));
                aB2 += ex2a(fmaf(ytB, u0.w, z0.w));
                if (!more) break;
                u0 = un; z0 = zn; g = gn;
            }
        }
        // ---- A masked bucket (~2 groups) ----
        for (g = G1 + l; g < GHA; g += 32) {
            float4 u0 = su4[g], z0 = sz4[g], y0 = sy4[g];
            float v0 = ex2a(fmaf(ytA, u0.x, z0.x));
            float v1 = ex2a(fmaf(ytA, u0.y, z0.y));
            float v2 = ex2a(fmaf(ytA, u0.z, z0.z));
            float v3 = ex2a(fmaf(ytA, u0.w, z0.w));
            if (y0.x < eA) aA  += v0;
            if (y0.y < eA) aA2 += v1;
            if (y0.z < eA) aA  += v2;
            if (y0.w < eA) aA2 += v3;
        }
        // ---- B masked bucket ----
        for (g = G2 + l; g < GHB; g += 32) {
            float4 u0 = su4[g], z0 = sz4[g], y0 = sy4[g];
            float v0 = ex2a(fmaf(ytB, u0.x, z0.x));
            float v1 = ex2a(fmaf(ytB, u0.y, z0.y));
            float v2 = ex2a(fmaf(ytB, u0.z, z0.z));
            float v3 = ex2a(fmaf(ytB, u0.w, z0.w));
            if (y0.x < eB) aB  += v0;
            if (y0.y < eB) aB2 += v1;
            if (y0.z < eB) aB  += v2;
            if (y0.w < eB) aB2 += v3;
        }
    }

    // warp reduce (full warp, full mask)
    float sA = aA + aA2;
    float sB = aB + aB2;
    #pragma unroll
    for (int o = 16; o; o >>= 1) {
        sA += __shfl_xor_sync(0xffffffffu, sA, o);
        sB += __shfl_xor_sync(0xffffffffu, sB, o);
    }

    if (l == 0) {
        const float LN2 = 0.6931471805599453f;
        float lp = 0.f, c = 0.f;
        float ymin = g_ymin;
        if (hasA) {
            float d = ytA - ymin;
            if (d > EPS) {
                float wv = uA * d;                       // log2(exp(logit_pos))
                lp += wv * LN2 - logf(ex2a(wv) + sA);
                c  += 1.f;
            }
        }
        if (hasB) {
            float d = ytB - ymin;
            if (d > EPS) {
                float wv = uB * d;
                lp += wv * LN2 - logf(ex2a(wv) + sB);
                c  += 1.f;
            }
        }
        rlp[w] = lp; rct[w] = c;
    }
    __syncthreads();

    // publish per-CTA partial, elect last block
    if (t == 0) {
        float tot = 0.f, c = 0.f;
        #pragma unroll
        for (int i = 0; i < SLOTS; i++) { tot += rlp[i]; c += rct[i]; }
        g_part[blockIdx.x] = make_float2(tot, c);
        __threadfence();
        int done = atomicAdd(&g_done, 1);
        s_last = (done == grid - 1) ? 1 : 0;
    }
    __syncthreads();

    // last block: deterministic final reduce
    if (s_last) {
        __threadfence();
        float tot = 0.f, cnt = 0.f;
        for (int i = t; i < grid; i += TPB) {
            float2 p = g_part[i]; tot += p.x; cnt += p.y;
        }
        #pragma unroll
        for (int o = 16; o; o >>= 1) {            // all threads, full warps
            tot += __shfl_xor_sync(0xffffffffu, tot, o);
            cnt += __shfl_xor_sync(0xffffffffu, cnt, o);
        }
        if ((t & 31) == 0) { ft[t >> 5] = tot; fc[t >> 5] = cnt; }
        __syncthreads();
        if (t == 0) {
            float a = 0.f, b = 0.f;
            #pragma unroll
            for (int i = 0; i < SLOTS; i++) { a += ft[i]; b += fc[i]; }
            out[0] = (b > 0.f) ? (-a / b) : 0.0f;
            g_done = 0;   // restore for next graph replay
        }
    }
}

// ------------- Launch --------------------------------------------------------
extern "C" void kernel_launch(void* const* d_in, const int* in_sizes, int n_in,
                              void* d_out, int out_size)
{
    const float* pred = (const float*)d_in[0];   // predict_similarity
    const float* yt   = (const float*)d_in[1];   // true_similarity
    int n = in_sizes[0];
    if (n > NMAX) n = NMAX;
    int padn = (n + 7) & ~7;
    if (padn > NMAX) padn = NMAX;

    int nslots = (n + 1) / 2;                    // 4096 for n=8192
    int grid = (nslots + SLOTS - 1) / SLOTS;     // 293
    if (grid > GMAX) grid = GMAX;

    pro_prep<<<1, 1024>>>(pred, yt, n, padn);
    pro_main<<<grid, TPB>>>((float*)d_out, n, grid);
}

// round 11
// speedup vs baseline: 1.6870x; 1.1141x over previous
#include <cuda_runtime.h>
#include <math.h>

#define NMAX  8192
#define NBKT  1024
#define TPB   896     // 28 warps; 1 warp = 1 row-pair slot
#define SLOTS 28
#define GMAX  512

__device__ float st_u [NMAX];         // sorted-by-yt: u = yp*20*log2e
__device__ float st_z [NMAX];         // z = -u*yt
__device__ float st_yt[NMAX];         // sorted yt
__device__ int   g_boff[NBKT + 1];    // bucket rank offsets
__device__ float g_ymin;
__device__ float2 g_part[GMAX];
__device__ int   g_done;              // zero-init; reset by last block each run

__device__ __forceinline__ float ex2a(float x) {
    float r; asm("ex2.approx.f32 %0, %1;" : "=f"(r) : "f"(x)); return r;
}

// ------------- Prep: counting sort staged through smem ----------------------
__global__ void __launch_bounds__(1024) pro_prep(const float* __restrict__ pred,
                                                 const float* __restrict__ ytg,
                                                 int n, int padn)
{
    __shared__ int   HA[NBKT], HB[NBKT];   // 8 KB
    __shared__ float SG[NMAX];             // 32 KB stage
    __shared__ float smn[32];
    const float K1 = 28.853900817779268f;  // 20 * log2(e)
    int t = threadIdx.x;

    HA[t] = 0;
    __syncthreads();

    float ry[8], rp[8];
    int   rb[8], rpos[8];
    float mn = 1e30f;

    #pragma unroll
    for (int e = 0; e < 8; e++) {
        int i = t + e * 1024;
        if (i < n) {
            float y = ytg[i], p = pred[i];
            ry[e] = y; rp[e] = p;
            int b = min(NBKT - 1, max(0, (int)floorf(y * (float)NBKT)));
            rb[e] = b;
            atomicAdd(&HA[b], 1);
            mn = fminf(mn, y);
        } else { ry[e] = 0.f; rp[e] = 0.f; rb[e] = -1; }
    }
    __syncthreads();

    // inclusive scan over 1024 buckets (1 elem/thread, double buffered)
    int* pa = HA; int* pb = HB;
    #pragma unroll
    for (int off = 1; off < NBKT; off <<= 1) {
        pb[t] = pa[t] + ((t >= off) ? pa[t - off] : 0);
        __syncthreads();
        int* tmp = pa; pa = pb; pb = tmp;
    }
    if (t == 0) g_boff[0] = 0;
    g_boff[t + 1] = pa[t];
    pb[t] = (t > 0) ? pa[t - 1] : 0;       // per-bucket running cursors
    __syncthreads();

    #pragma unroll
    for (int e = 0; e < 8; e++)
        if (rb[e] >= 0) rpos[e] = atomicAdd(&pb[rb[e]], 1);
    __syncthreads();

    // pass 1: u
    #pragma unroll
    for (int e = 0; e < 8; e++) if (rb[e] >= 0) SG[rpos[e]] = rp[e] * K1;
    __syncthreads();
    #pragma unroll
    for (int e = 0; e < 8; e++) { int i = t + e * 1024; if (i < n) st_u[i] = SG[i]; }
    __syncthreads();
    // pass 2: z = -u*yt
    #pragma unroll
    for (int e = 0; e < 8; e++) if (rb[e] >= 0) SG[rpos[e]] = -(rp[e] * K1) * ry[e];
    __syncthreads();
    #pragma unroll
    for (int e = 0; e < 8; e++) { int i = t + e * 1024; if (i < n) st_z[i] = SG[i]; }
    __syncthreads();
    // pass 3: yt
    #pragma unroll
    for (int e = 0; e < 8; e++) if (rb[e] >= 0) SG[rpos[e]] = ry[e];
    __syncthreads();
    #pragma unroll
    for (int e = 0; e < 8; e++) { int i = t + e * 1024; if (i < n) st_yt[i] = SG[i]; }
    // padding
    for (int i = n + t; i < padn; i += 1024) { st_u[i] = 0.f; st_z[i] = 0.f; st_yt[i] = 1e30f; }

    // global min
    #pragma unroll
    for (int o = 16; o; o >>= 1) mn = fminf(mn, __shfl_xor_sync(0xffffffffu, mn, o));
    if ((t & 31) == 0) smn[t >> 5] = mn;
    __syncthreads();
    if (t < 32) {
        float v = smn[t];
        #pragma unroll
        for (int o = 16; o; o >>= 1) v = fminf(v, __shfl_xor_sync(0xffffffffu, v, o));
        if (t == 0) g_ymin = v;
    }
}

// ------------- Main: one warp per slot, one wave, fused finish ---------------
__global__ void __launch_bounds__(TPB) pro_main(float* __restrict__ out,
                                                int n, int grid)
{
    __shared__ float rlp[SLOTS], rct[SLOTS];
    __shared__ int   s_last;
    __shared__ float ft[SLOTS], fc[SLOTS];

    const float EPS = 1e-8f;
    int t = threadIdx.x, w = t >> 5, l = t & 31;
    int q = blockIdx.x * SLOTS + w;

    bool hasA = (2 * q <= n - 1);
    bool hasB = (2 * q <  n - 1);
    int rA = q, rB = n - 1 - q;

    float ytA = 0.f, uA = 0.f, eA = 0.f; int cLoA = 0, cHiA = 0;
    float ytB = 0.f, uB = 0.f, eB = 0.f; int cLoB = 0, cHiB = 0;
    if (hasA) {
        ytA = st_yt[rA]; uA = st_u[rA]; eA = ytA - EPS;
        int b = min(NBKT - 1, max(0, (int)floorf(eA * (float)NBKT)));
        cLoA = g_boff[b]; cHiA = g_boff[b + 1];
    }
    if (hasB) {
        ytB = st_yt[rB]; uB = st_u[rB]; eB = ytB - EPS;
        int b = min(NBKT - 1, max(0, (int)floorf(eB * (float)NBKT)));
        cLoB = g_boff[b]; cHiB = g_boff[b + 1];
    } else { ytB = ytA; eB = eA; cLoB = cLoA; cHiB = cLoA; }

    float aA = 0.f, aA2 = 0.f, aB = 0.f, aB2 = 0.f;
    const float4* su4 = (const float4*)st_u;
    const float4* sz4 = (const float4*)st_z;
    const float4* sy4 = (const float4*)st_yt;

    int G1  = cLoA >> 2;            // groups fully valid for BOTH rows
    int G2  = cLoB >> 2;            // groups fully valid for B
    int GHA = (cHiA + 3) >> 2;
    int GHB = (cHiB + 3) >> 2;

    if (hasA) {
        // shared fast loop: 8 exps per 2 loads, no masks
        #pragma unroll 2
        for (int g = l; g < G1; g += 32) {
            float4 u0 = su4[g], z0 = sz4[g];
            aA  += ex2a(fmaf(ytA, u0.x, z0.x));
            aA2 += ex2a(fmaf(ytA, u0.y, z0.y));
            aA  += ex2a(fmaf(ytA, u0.z, z0.z));
            aA2 += ex2a(fmaf(ytA, u0.w, z0.w));
            aB  += ex2a(fmaf(ytB, u0.x, z0.x));
            aB2 += ex2a(fmaf(ytB, u0.y, z0.y));
            aB  += ex2a(fmaf(ytB, u0.z, z0.z));
            aB2 += ex2a(fmaf(ytB, u0.w, z0.w));
        }
        // B-only fast loop
        #pragma unroll 2
        for (int g = G1 + l; g < G2; g += 32) {
            float4 u0 = su4[g], z0 = sz4[g];
            aB  += ex2a(fmaf(ytB, u0.x, z0.x));
            aB2 += ex2a(fmaf(ytB, u0.y, z0.y));
            aB  += ex2a(fmaf(ytB, u0.z, z0.z));
            aB2 += ex2a(fmaf(ytB, u0.w, z0.w));
        }
        // A masked bucket (~2 groups)
        for (int g = G1 + l; g < GHA; g += 32) {
            float4 u0 = su4[g], z0 = sz4[g], y0 = sy4[g];
            float v0 = ex2a(fmaf(ytA, u0.x, z0.x));
            float v1 = ex2a(fmaf(ytA, u0.y, z0.y));
            float v2 = ex2a(fmaf(ytA, u0.z, z0.z));
            float v3 = ex2a(fmaf(ytA, u0.w, z0.w));
            if (y0.x < eA) aA  += v0;
            if (y0.y < eA) aA2 += v1;
            if (y0.z < eA) aA  += v2;
            if (y0.w < eA) aA2 += v3;
        }
        // B masked bucket
        for (int g = G2 + l; g < GHB; g += 32) {
            float4 u0 = su4[g], z0 = sz4[g], y0 = sy4[g];
            float v0 = ex2a(fmaf(ytB, u0.x, z0.x));
            float v1 = ex2a(fmaf(ytB, u0.y, z0.y));
            float v2 = ex2a(fmaf(ytB, u0.z, z0.z));
            float v3 = ex2a(fmaf(ytB, u0.w, z0.w));
            if (y0.x < eB) aB  += v0;
            if (y0.y < eB) aB2 += v1;
            if (y0.z < eB) aB  += v2;
            if (y0.w < eB) aB2 += v3;
        }
    }

    // warp reduce (full warp, full mask)
    float sA = aA + aA2;
    float sB = aB + aB2;
    #pragma unroll
    for (int o = 16; o; o >>= 1) {
        sA += __shfl_xor_sync(0xffffffffu, sA, o);
        sB += __shfl_xor_sync(0xffffffffu, sB, o);
    }

    if (l == 0) {
        const float LN2 = 0.6931471805599453f;
        float lp = 0.f, c = 0.f;
        float ymin = g_ymin;
        if (hasA) {
            float d = ytA - ymin;
            if (d > EPS) {
                float wv = uA * d;                   // log2 of exp(logit_pos)
                lp += wv * LN2 - logf(ex2a(wv) + sA);
                c  += 1.f;
            }
        }
        if (hasB) {
            float d = ytB - ymin;
            if (d > EPS) {
                float wv = uB * d;
                lp += wv * LN2 - logf(ex2a(wv) + sB);
                c  += 1.f;
            }
        }
        rlp[w] = lp; rct[w] = c;
    }
    __syncthreads();

    // publish per-CTA partial, elect last block
    if (t == 0) {
        float tot = 0.f, c = 0.f;
        #pragma unroll
        for (int i = 0; i < SLOTS; i++) { tot += rlp[i]; c += rct[i]; }
        g_part[blockIdx.x] = make_float2(tot, c);
        __threadfence();
        int done = atomicAdd(&g_done, 1);
        s_last = (done == grid - 1) ? 1 : 0;
    }
    __syncthreads();

    // last block: deterministic final reduce
    if (s_last) {
        __threadfence();
        float tot = 0.f, cnt = 0.f;
        for (int i = t; i < grid; i += TPB) {
            float2 p = g_part[i]; tot += p.x; cnt += p.y;
        }
        #pragma unroll
        for (int o = 16; o; o >>= 1) {            // all threads, full warps
            tot += __shfl_xor_sync(0xffffffffu, tot, o);
            cnt += __shfl_xor_sync(0xffffffffu, cnt, o);
        }
        if ((t & 31) == 0) { ft[t >> 5] = tot; fc[t >> 5] = cnt; }
        __syncthreads();
        if (t == 0) {
            float a = 0.f, b = 0.f;
            #pragma unroll
            for (int i = 0; i < SLOTS; i++) { a += ft[i]; b += fc[i]; }
            out[0] = (b > 0.f) ? (-a / b) : 0.0f;
            g_done = 0;   // restore for next graph replay
        }
    }
}

// ------------- Launch --------------------------------------------------------
extern "C" void kernel_launch(void* const* d_in, const int* in_sizes, int n_in,
                              void* d_out, int out_size)
{
    const float* pred = (const float*)d_in[0];   // predict_similarity
    const float* yt   = (const float*)d_in[1];   // true_similarity
    int n = in_sizes[0];
    if (n > NMAX) n = NMAX;
    int padn = (n + 7) & ~7;
    if (padn > NMAX) padn = NMAX;

    int nslots = (n + 1) / 2;                    // 4096 for n=8192
    int grid = (nslots + SLOTS - 1) / SLOTS;     // 147 -> one CTA per SM, one wave
    if (grid > GMAX) grid = GMAX;

    pro_prep<<<1, 1024>>>(pred, yt, n, padn);
    pro_main<<<grid, TPB>>>((float*)d_out, n, grid);
}